// round 1
// baseline (speedup 1.0000x reference)
#include <cuda_runtime.h>
#include <math.h>

#define B_   4
#define LQ   1024
#define LK   2048
#define H_   8
#define HID  256
#define D_   32
#define IN_  13          // augmented inner dim: 8 spatial + 3 wave + 1 + 1
#define TEMP_INV 10.0f   // 1/TEMP

// ---------------- scratch (device globals; no allocations) ----------------
__device__ float g_G[H_ * 12 * 12];                 // per-head bilinear form
__device__ float g_R[88 * HID];                     // fused Av_h @ Wo_h^T   [h*11+j][o]
__device__ float g_obias[HID];                      // bo + bv @ Wo^T
__device__ float g_Q[(size_t)B_ * H_ * IN_ * LQ];   // Q-hat, transposed [bh][kk][q]
__device__ float g_K[(size_t)B_ * H_ * IN_ * LK];   // K-hat, transposed [bh][kk][k]
__device__ float g_V[(size_t)B_ * LK * 12];         // raw v_ret padded to 12
__device__ float g_cr[(size_t)B_ * LQ * 88];        // ctxRaw [b*LQ+q][h*11+j]

__device__ __forceinline__ float sigmoidf_(float x) { return 1.f / (1.f + expf(-x)); }

// ---------------- P0: fold weights into G_h, R, obias ----------------
__global__ void p0_params(const float* __restrict__ Wq_s, const float* __restrict__ bq_s,
                          const float* __restrict__ Wk_s, const float* __restrict__ bk_s,
                          const float* __restrict__ Wq_w, const float* __restrict__ bq_w,
                          const float* __restrict__ Wk_w, const float* __restrict__ bk_w,
                          const float* __restrict__ Wv,   const float* __restrict__ bv,
                          const float* __restrict__ Wo,   const float* __restrict__ bo,
                          const float* __restrict__ wb)
{
    int t = threadIdx.x;
    int blk = blockIdx.x;
    if (blk == H_) {
        // obias[o] = bo[o] + sum_t bv[t]*Wo[o,t]
        float acc = bo[t];
        for (int u = 0; u < HID; u++) acc += bv[u] * Wo[t * HID + u];
        g_obias[t] = acc;
        return;
    }
    int h = blk;
    float alpha = sigmoidf_(wb[0]);
    float c1 = (1.f - alpha) / sqrtf((float)D_);
    float c2 = 2.f * alpha * TEMP_INV;

    if (t < 144) {
        int r = t / 12, c = t % 12;
        float acc = 0.f;
        if (r < 8 && c < 8) {
            for (int d = 0; d < 32; d++) acc += Wq_s[(h*32+d)*8 + r] * Wk_s[(h*32+d)*8 + c];
            acc *= c1;
        } else if (r < 8 && c == 11) {
            for (int d = 0; d < 32; d++) acc += Wq_s[(h*32+d)*8 + r] * bk_s[h*32+d];
            acc *= c1;
        } else if (r >= 8 && r < 11 && c >= 8 && c < 11) {
            for (int d = 0; d < 32; d++) acc += Wq_w[(h*32+d)*3 + (r-8)] * Wk_w[(h*32+d)*3 + (c-8)];
            acc *= c2;
        } else if (r >= 8 && r < 11 && c == 11) {
            for (int d = 0; d < 32; d++) acc += Wq_w[(h*32+d)*3 + (r-8)] * bk_w[h*32+d];
            acc *= c2;
        } else if (r == 11 && c < 8) {
            for (int d = 0; d < 32; d++) acc += bq_s[h*32+d] * Wk_s[(h*32+d)*8 + c];
            acc *= c1;
        } else if (r == 11 && c >= 8 && c < 11) {
            for (int d = 0; d < 32; d++) acc += bq_w[h*32+d] * Wk_w[(h*32+d)*3 + (c-8)];
            acc *= c2;
        } else if (r == 11 && c == 11) {
            float a1 = 0.f, a2 = 0.f;
            for (int d = 0; d < 32; d++) {
                a1 += bq_s[h*32+d] * bk_s[h*32+d];
                a2 += bq_w[h*32+d] * bk_w[h*32+d];
            }
            acc = c1 * a1 + c2 * a2;
        }
        g_G[(h*12 + r)*12 + c] = acc;
    }
    // R_h[j][o] = sum_d Wv[(h*32+d)*11+j] * Wo[o*256 + h*32+d]
    float wo[32];
    #pragma unroll
    for (int d = 0; d < 32; d++) wo[d] = Wo[t * HID + h*32 + d];
    for (int j = 0; j < 11; j++) {
        float acc = 0.f;
        #pragma unroll
        for (int d = 0; d < 32; d++) acc += Wv[(h*32+d)*11 + j] * wo[d];
        g_R[(h*11 + j) * HID + t] = acc;
    }
}

// ---------------- P1q: build Q-hat (transposed) ----------------
__global__ void __launch_bounds__(128)
p1_q(const float* __restrict__ q_fp, const float* __restrict__ Wq_w,
     const float* __restrict__ bq_w, const float* __restrict__ wb)
{
    __shared__ float Gs[H_ * 144];
    __shared__ float Ws[HID * 3];
    __shared__ float Bs[HID];
    int t = threadIdx.x;
    for (int i = t; i < H_ * 144; i += 128) Gs[i] = g_G[i];
    for (int i = t; i < HID * 3;  i += 128) Ws[i] = Wq_w[i];
    for (int i = t; i < HID;      i += 128) Bs[i] = bq_w[i];
    __syncthreads();

    float alpha = sigmoidf_(wb[0]);
    float beta = alpha * TEMP_INV;
    int idx = blockIdx.x * 128 + t;   // b*LQ + q
    int b = idx >> 10, q = idx & (LQ - 1);

    float x[11];
    #pragma unroll
    for (int j = 0; j < 11; j++) x[j] = q_fp[(size_t)idx * 11 + j];

    for (int h = 0; h < H_; h++) {
        float qn = 0.f;
        #pragma unroll 4
        for (int d = 0; d < 32; d++) {
            float s = Bs[h*32 + d];
            s += x[8]  * Ws[(h*32+d)*3 + 0];
            s += x[9]  * Ws[(h*32+d)*3 + 1];
            s += x[10] * Ws[(h*32+d)*3 + 2];
            qn += s * s;
        }
        size_t base = ((size_t)(b * H_ + h) * IN_) * LQ + q;
        const float* Gh = &Gs[h * 144];
        #pragma unroll
        for (int c = 0; c < 12; c++) {
            float a = Gh[11*12 + c];
            #pragma unroll
            for (int r = 0; r < 11; r++) a += x[r] * Gh[r*12 + c];
            if (c == 11) a -= beta * qn;
            g_Q[base + (size_t)c * LQ] = a;
        }
        g_Q[base + (size_t)12 * LQ] = 1.f;
    }
}

// ---------------- P1k: build K-hat (transposed) + padded V ----------------
__global__ void __launch_bounds__(128)
p1_k(const float* __restrict__ v_ret, const float* __restrict__ Wk_w,
     const float* __restrict__ bk_w, const float* __restrict__ wb)
{
    __shared__ float Ws[HID * 3];
    __shared__ float Bs[HID];
    int t = threadIdx.x;
    for (int i = t; i < HID * 3; i += 128) Ws[i] = Wk_w[i];
    for (int i = t; i < HID;     i += 128) Bs[i] = bk_w[i];
    __syncthreads();

    float alpha = sigmoidf_(wb[0]);
    float beta = alpha * TEMP_INV;
    int idx = blockIdx.x * 128 + t;   // b*LK + k
    int b = idx >> 11, k = idx & (LK - 1);

    float x[11];
    #pragma unroll
    for (int j = 0; j < 11; j++) x[j] = v_ret[(size_t)idx * 11 + j];

    #pragma unroll
    for (int c = 0; c < 11; c++) g_V[(size_t)idx * 12 + c] = x[c];
    g_V[(size_t)idx * 12 + 11] = 0.f;

    for (int h = 0; h < H_; h++) {
        float kn = 0.f;
        #pragma unroll 4
        for (int d = 0; d < 32; d++) {
            float s = Bs[h*32 + d];
            s += x[8]  * Ws[(h*32+d)*3 + 0];
            s += x[9]  * Ws[(h*32+d)*3 + 1];
            s += x[10] * Ws[(h*32+d)*3 + 2];
            kn += s * s;
        }
        size_t base = ((size_t)(b * H_ + h) * IN_) * LK + k;
        #pragma unroll
        for (int j = 0; j < 11; j++) g_K[base + (size_t)j * LK] = x[j];
        g_K[base + (size_t)11 * LK] = 1.f;
        g_K[base + (size_t)12 * LK] = -beta * kn;
    }
}

// ---------------- main flash-attention kernel (fp32 SIMT) ----------------
__global__ void __launch_bounds__(256, 2)
attn_kernel(const float* __restrict__ pi)
{
    __shared__ float Qs[IN_][64];
    __shared__ float Ks[IN_][64];
    __shared__ float Vs[64 * 12];

    int t = threadIdx.x;
    int tx = t & 15, ty = t >> 4;
    int h = blockIdx.x, qt = blockIdx.y, b = blockIdx.z;
    int bh = b * H_ + h;
    int q0 = qt * 64;

    for (int i = t; i < IN_ * 64; i += 256) {
        int kk = i >> 6, col = i & 63;
        Qs[kk][col] = g_Q[((size_t)bh * IN_ + kk) * LQ + q0 + col];
    }

    float O[4][11];
    float m[4], l[4];
    #pragma unroll
    for (int i = 0; i < 4; i++) {
        m[i] = -1e30f; l[i] = 0.f;
        #pragma unroll
        for (int c = 0; c < 11; c++) O[i][c] = 0.f;
    }

    const float* piP = pi + ((size_t)(b * LQ + q0 + ty * 4)) * LK + tx * 4;

    for (int kt = 0; kt < LK / 64; kt++) {
        int k0 = kt * 64;
        // prefetch transport mask tile (hides LDG latency behind smem fills)
        float4 pv[4];
        #pragma unroll
        for (int i = 0; i < 4; i++)
            pv[i] = *(const float4*)(piP + (size_t)i * LK + k0);

        __syncthreads();
        for (int i = t; i < IN_ * 64; i += 256) {
            int kk = i >> 6, col = i & 63;
            Ks[kk][col] = g_K[((size_t)bh * IN_ + kk) * LK + k0 + col];
        }
        {
            const float4* src = (const float4*)(g_V + ((size_t)b * LK + k0) * 12);
            float4* dst = (float4*)Vs;
            for (int i = t; i < 192; i += 256) dst[i] = src[i];
        }
        __syncthreads();

        // S = Qhat . Khat   (inner dim 13)
        float S[4][4];
        #pragma unroll
        for (int i = 0; i < 4; i++)
            #pragma unroll
            for (int j = 0; j < 4; j++) S[i][j] = 0.f;

        #pragma unroll
        for (int kk = 0; kk < IN_; kk++) {
            float4 a4 = *(const float4*)&Qs[kk][ty * 4];
            float4 b4 = *(const float4*)&Ks[kk][tx * 4];
            float av[4] = {a4.x, a4.y, a4.z, a4.w};
            float bw[4] = {b4.x, b4.y, b4.z, b4.w};
            #pragma unroll
            for (int i = 0; i < 4; i++)
                #pragma unroll
                for (int j = 0; j < 4; j++) S[i][j] += av[i] * bw[j];
        }

        // + log(clip(pi, 1e-9))
        #pragma unroll
        for (int i = 0; i < 4; i++) {
            S[i][0] += __logf(fmaxf(pv[i].x, 1e-9f));
            S[i][1] += __logf(fmaxf(pv[i].y, 1e-9f));
            S[i][2] += __logf(fmaxf(pv[i].z, 1e-9f));
            S[i][3] += __logf(fmaxf(pv[i].w, 1e-9f));
        }

        // online softmax (row max shared across the 16 tx lanes; l kept partial)
        #pragma unroll
        for (int i = 0; i < 4; i++) {
            float tm = fmaxf(fmaxf(S[i][0], S[i][1]), fmaxf(S[i][2], S[i][3]));
            tm = fmaxf(tm, __shfl_xor_sync(0xffffffffu, tm, 1));
            tm = fmaxf(tm, __shfl_xor_sync(0xffffffffu, tm, 2));
            tm = fmaxf(tm, __shfl_xor_sync(0xffffffffu, tm, 4));
            tm = fmaxf(tm, __shfl_xor_sync(0xffffffffu, tm, 8));
            float nm = fmaxf(m[i], tm);
            float cf = __expf(m[i] - nm);
            m[i] = nm;
            float rs = 0.f;
            #pragma unroll
            for (int j = 0; j < 4; j++) { S[i][j] = __expf(S[i][j] - nm); rs += S[i][j]; }
            l[i] = l[i] * cf + rs;
            #pragma unroll
            for (int c = 0; c < 11; c++) O[i][c] *= cf;
        }

        // O += P . v_ret (each tx lane owns its 4 key columns; inner dim 11)
        #pragma unroll
        for (int jj = 0; jj < 4; jj++) {
            const float* vr = &Vs[(tx * 4 + jj) * 12];
            float4 v0 = *(const float4*)vr;
            float4 v1 = *(const float4*)(vr + 4);
            float4 v2 = *(const float4*)(vr + 8);
            float vv[11] = {v0.x, v0.y, v0.z, v0.w, v1.x, v1.y, v1.z, v1.w, v2.x, v2.y, v2.z};
            #pragma unroll
            for (int i = 0; i < 4; i++) {
                float p = S[i][jj];
                #pragma unroll
                for (int c = 0; c < 11; c++) O[i][c] += p * vv[c];
            }
        }
    }

    // reduce partial O and l across the 16 tx lanes (within half-warp)
    #pragma unroll
    for (int i = 0; i < 4; i++) {
        l[i] += __shfl_xor_sync(0xffffffffu, l[i], 1);
        l[i] += __shfl_xor_sync(0xffffffffu, l[i], 2);
        l[i] += __shfl_xor_sync(0xffffffffu, l[i], 4);
        l[i] += __shfl_xor_sync(0xffffffffu, l[i], 8);
        #pragma unroll
        for (int c = 0; c < 11; c++) {
            O[i][c] += __shfl_xor_sync(0xffffffffu, O[i][c], 1);
            O[i][c] += __shfl_xor_sync(0xffffffffu, O[i][c], 2);
            O[i][c] += __shfl_xor_sync(0xffffffffu, O[i][c], 4);
            O[i][c] += __shfl_xor_sync(0xffffffffu, O[i][c], 8);
        }
    }

    if (tx == 0) {
        #pragma unroll
        for (int i = 0; i < 4; i++) {
            float inv = 1.0f / l[i];
            size_t base = ((size_t)(b * LQ + q0 + ty * 4 + i)) * 88 + h * 11;
            #pragma unroll
            for (int c = 0; c < 11; c++) g_cr[base + c] = O[i][c] * inv;
        }
    }
}

// ---------------- epilogue: out = ctxRaw(4096x88) @ R(88x256) + obias ----------------
__global__ void __launch_bounds__(256)
epilogue_kernel(float* __restrict__ out)
{
    __shared__ float crsT[88][32];
    int t = threadIdx.x;
    int row0 = blockIdx.x * 32;

    for (int i = t; i < 32 * 88; i += 256) {
        int r = i / 88, j = i % 88;
        crsT[j][r] = g_cr[(size_t)(row0 + r) * 88 + j];
    }
    __syncthreads();

    float acc[32];
    #pragma unroll
    for (int r = 0; r < 32; r++) acc[r] = 0.f;

    #pragma unroll 4
    for (int j = 0; j < 88; j++) {
        float rv = g_R[j * HID + t];
        #pragma unroll
        for (int r = 0; r < 32; r += 4) {
            float4 cv = *(const float4*)&crsT[j][r];
            acc[r]     += cv.x * rv;
            acc[r + 1] += cv.y * rv;
            acc[r + 2] += cv.z * rv;
            acc[r + 3] += cv.w * rv;
        }
    }

    float ob = g_obias[t];
    for (int r = 0; r < 32; r++)
        out[(size_t)(row0 + r) * HID + t] = acc[r] + ob;
}

// ---------------- launch ----------------
extern "C" void kernel_launch(void* const* d_in, const int* in_sizes, int n_in,
                              void* d_out, int out_size)
{
    const float* q_fp  = (const float*)d_in[0];
    const float* v_ret = (const float*)d_in[1];
    const float* pi    = (const float*)d_in[2];
    const float* Wq_s  = (const float*)d_in[3];
    const float* bq_s  = (const float*)d_in[4];
    const float* Wk_s  = (const float*)d_in[5];
    const float* bk_s  = (const float*)d_in[6];
    const float* Wq_w  = (const float*)d_in[7];
    const float* bq_w  = (const float*)d_in[8];
    const float* Wk_w  = (const float*)d_in[9];
    const float* bk_w  = (const float*)d_in[10];
    const float* Wv    = (const float*)d_in[11];
    const float* bv    = (const float*)d_in[12];
    const float* Wo    = (const float*)d_in[13];
    const float* bo    = (const float*)d_in[14];
    const float* wb    = (const float*)d_in[15];
    float* out = (float*)d_out;

    p0_params<<<H_ + 1, 256>>>(Wq_s, bq_s, Wk_s, bk_s, Wq_w, bq_w, Wk_w, bk_w,
                               Wv, bv, Wo, bo, wb);
    p1_q<<<(B_ * LQ) / 128, 128>>>(q_fp, Wq_w, bq_w, wb);
    p1_k<<<(B_ * LK) / 128, 128>>>(v_ret, Wk_w, bk_w, wb);
    dim3 g(H_, LQ / 64, B_);
    attn_kernel<<<g, 256>>>(pi);
    epilogue_kernel<<<(B_ * LQ) / 32, 256>>>(out);
}